// round 17
// baseline (speedup 1.0000x reference)
#include <cuda_runtime.h>
#include <stdint.h>

#define TT 2048
#define BB 32
#define HH 512
#define NB 64
#define CPB 8

// ---- main kernel SMEM (bytes) ----
#define SM_A   1024
#define SM_B   (SM_A + 131072)          // A: 32 rows x 4KB [dead x 2KB | h_hi 1KB | h_lo 1KB]
#define SM_TOT (SM_B + 49152)           // B: 24 rows x 2KB  -> 181248

// main scratch: 4 k-quarter regions in the dead x-region (float indices)
#define K0 0
#define K1 800
#define K2 1600
#define K3 2400

// ---- prepass P1 SMEM ----
#define P1_A   0
#define P1_B   131072                   // A: 64 rows x 2KB
#define P1_S   (131072 + 49152)         // B: 24 rows x 2KB; scratch 2x1600 floats
#define P1_TOT (P1_S + 12800)           // 193024

// ----------------------------------------------------------------------------
// Device scratch
// ----------------------------------------------------------------------------
__device__ __align__(16) float          g_G[(size_t)TT * 2 * NB * BB * 24];   // 805MB preacts
__device__ __align__(16) unsigned short g_xs[(size_t)TT * BB * 1024];         // x split-bf16 planes
__device__ __align__(16) unsigned short g_gw[2 * NB * 24 * 1024];             // Wxi split planes
__device__ __align__(16) unsigned short g_hh[2][2][BB * HH];
__device__ __align__(16) unsigned short g_hl[2][2][BB * HH];
__device__ unsigned g_grp[2][8];
__device__ unsigned g_root[2];

struct Args {
    const float* x;
    const float* Wxi[2][3];
    const float* Whh[2][3];
    const float* br[2];
    const float* bi[2];
    const float* bni[2];
    const float* bnh[2];
    float*       out;
};

// ----------------------------------------------------------------------------
// Helpers
// ----------------------------------------------------------------------------
__device__ __forceinline__ uint32_t smem_u32(const void* p_) {
    uint32_t a;
    asm("{ .reg .u64 t; cvta.to.shared.u64 t, %1; cvt.u32.u64 %0, t; }" : "=r"(a) : "l"(p_));
    return a;
}
__device__ __forceinline__ unsigned packbf(float lo, float hi) {
    unsigned d;
    asm("cvt.rn.bf16x2.f32 %0, %1, %2;" : "=r"(d) : "f"(hi), "f"(lo));
    return d;
}
__device__ __forceinline__ unsigned short cvtbf(float f) {
    unsigned short h;
    asm("cvt.rn.bf16.f32 %0, %1;" : "=h"(h) : "f"(f));
    return h;
}
__device__ __forceinline__ float lo16f(unsigned u) { return __uint_as_float(u << 16); }
__device__ __forceinline__ float hi16f(unsigned u) { return __uint_as_float(u & 0xffff0000u); }

__device__ __forceinline__ void split8(float4 a, float4 b, uint4& h, uint4& l) {
    h.x = packbf(a.x, a.y);  h.y = packbf(a.z, a.w);
    h.z = packbf(b.x, b.y);  h.w = packbf(b.z, b.w);
    l.x = packbf(a.x - lo16f(h.x), a.y - hi16f(h.x));
    l.y = packbf(a.z - lo16f(h.y), a.w - hi16f(h.y));
    l.z = packbf(b.x - lo16f(h.z), b.y - hi16f(h.z));
    l.w = packbf(b.z - lo16f(h.w), b.w - hi16f(h.w));
}

__device__ __forceinline__ unsigned atom_add_ar(unsigned* p_, unsigned v) {
    unsigned o;
    asm volatile("atom.acq_rel.gpu.add.u32 %0, [%1], %2;" : "=r"(o) : "l"(p_), "r"(v) : "memory");
    return o;
}
__device__ __forceinline__ unsigned ld_acq(const unsigned* p_) {
    unsigned v;
    asm volatile("ld.acquire.gpu.u32 %0, [%1];" : "=r"(v) : "l"(p_) : "memory");
    return v;
}
__device__ __forceinline__ void net_arrive(int d, int g) {
    unsigned a = atom_add_ar(&g_grp[d][g], 1u);
    if (((a + 1u) & 7u) == 0u) atom_add_ar(&g_root[d], 1u);
}

__device__ __forceinline__ float fsig(float z) {
    return __fdividef(1.0f, 1.0f + __expf(-z));
}
__device__ __forceinline__ float ftanh(float z) {
    float a = fabsf(z), e = __expf(-2.0f * a);
    return copysignf(__fdividef(1.0f - e, 1.0f + e), z);
}

// main scratch accessor: x-region bytes of A rows 0..6
__device__ __forceinline__ float* scx(char* smem, int idx) {
    return (float*)(smem + SM_A + ((idx >> 9) << 12) + ((idx & 511) << 2));
}

#define LDX4(R, ADDR)                                                           \
    asm volatile("ldmatrix.sync.aligned.m8n8.x4.shared.b16 {%0,%1,%2,%3}, [%4];" \
        : "=r"((R)[0]), "=r"((R)[1]), "=r"((R)[2]), "=r"((R)[3]) : "r"(ADDR))

#define MMA4(C, A, B0, B1)                                                      \
    asm volatile("mma.sync.aligned.m16n8k16.row.col.f32.bf16.bf16.f32 "         \
        "{%0,%1,%2,%3}, {%4,%5,%6,%7}, {%8,%9}, {%0,%1,%2,%3};"                 \
        : "+f"((C)[0]), "+f"((C)[1]), "+f"((C)[2]), "+f"((C)[3])                \
        : "r"((A)[0]), "r"((A)[1]), "r"((A)[2]), "r"((A)[3]), "r"(B0), "r"(B1))

// Shared MMA segment macro: needs aRow,aXor,kcA,bR0..2,bXor,kcB,acc0..2 in scope
#define SEGRUN(AOFF, BOFF, D0, D1)                                              \
    _Pragma("unroll")                                                           \
    for (int dd = (D0); dd < (D1); ++dd) {                                      \
        uint32_t ca = (uint32_t)((((AOFF) + dd * 32) >> 3)) + kcA;              \
        uint32_t cb = (uint32_t)((((BOFF) + dd * 32) >> 3)) + kcB;              \
        uint32_t fa0[4], fa1[4], fb0[4], fb1[4], fb2[4];                        \
        LDX4(fa0, aRow + ((ca ^ aXor) << 4));                                   \
        LDX4(fa1, aRow + (((ca + 2) ^ aXor) << 4));                             \
        LDX4(fb0, bR0 + ((cb ^ bXor) << 4));                                    \
        LDX4(fb1, bR1 + ((cb ^ bXor) << 4));                                    \
        LDX4(fb2, bR2 + ((cb ^ bXor) << 4));                                    \
        MMA4(acc0, fa0, fb0[0], fb0[1]);                                        \
        MMA4(acc1, fa0, fb1[0], fb1[1]);                                        \
        MMA4(acc2, fa0, fb2[0], fb2[1]);                                        \
        MMA4(acc0, fa1, fb0[2], fb0[3]);                                        \
        MMA4(acc1, fa1, fb1[2], fb1[3]);                                        \
        MMA4(acc2, fa1, fb2[2], fb2[3]);                                        \
    }

// ----------------------------------------------------------------------------
// P0: Wxi -> g_gw (split-bf16, transposed [n][k], swizzled rows of 2KB)
// ----------------------------------------------------------------------------
__global__ void __launch_bounds__(256) prep_w(Args p)
{
    const int tid = threadIdx.x;
    const int db = blockIdx.x;            // dir*64 + blk
    const int dir = db >> 6, blk = db & 63, j0 = blk * CPB;
    unsigned short* dst = g_gw + (size_t)db * 24 * 1024;
    for (int idx = tid; idx < 24 * 512; idx += 256) {
        int n = idx >> 9, k = idx & 511;
        int gate = n >> 3, jl = n & 7;
        float v = p.Wxi[dir][gate][(size_t)k * HH + j0 + jl];
        unsigned short hb = cvtbf(v);
        unsigned short lb = cvtbf(v - __uint_as_float((unsigned)hb << 16));
        int x7 = n & 7, kc = k >> 3, kb = k & 7;
        unsigned short* row = dst + n * 1024;
        row[((kc ^ x7) << 3) + kb] = hb;
        row[512 + ((kc ^ x7) << 3) + kb] = lb;
    }
}

// ----------------------------------------------------------------------------
// P0b: x -> g_xs (split-bf16 rows [hi 512 | lo 512], chunk swizzle ^ (b&7))
// ----------------------------------------------------------------------------
__global__ void __launch_bounds__(256) prep_x(const float* __restrict__ x)
{
    const int gid = blockIdx.x * 256 + threadIdx.x;   // 0..4194303
    const int row = gid >> 6, k8 = gid & 63;          // row = t*32 + b
    const int x7 = row & 7;                            // == b & 7
    const float4* sp = (const float4*)(x + (size_t)row * HH + k8 * 8);
    float4 a = __ldg(sp), b4 = __ldg(sp + 1);
    uint4 h4, l4;
    split8(a, b4, h4, l4);
    unsigned short* dr = g_xs + (size_t)row * 1024;
    *(uint4*)(dr + ((k8 ^ x7) << 3)) = h4;
    *(uint4*)(dr + 512 + ((k8 ^ x7) << 3)) = l4;
}

// ----------------------------------------------------------------------------
// P1: G[t][dir][blk][b][24] = x(t) . Wxi  (no bias). CTA: 2 timesteps resident,
// loops all 128 (dir,blk). Warps: m-tile(4 of 16 rows) x k-half(2).
// ----------------------------------------------------------------------------
__global__ void __launch_bounds__(256, 1) prep_g()
{
    extern __shared__ char smem[];
    const uint32_t su = smem_u32(smem);
    const int tid = threadIdx.x, wid = tid >> 5, lane = tid & 31;
    const int tg = blockIdx.x;            // 0..1023

    // A copy: 64 rows (2t x 32b) x 2KB, verbatim (swizzle baked into g_xs)
    {
        const uint4* src = (const uint4*)(g_xs + (size_t)tg * 2 * BB * 1024);
        uint4* dst = (uint4*)(smem + P1_A);
        #pragma unroll
        for (int i = 0; i < 32; ++i) dst[tid + i * 256] = __ldg(src + tid + i * 256);
    }
    __syncthreads();

    const int mt = wid & 3, kh = wid >> 2;
    const int rA = mt * 16 + (lane & 7) + ((lane >> 3) & 1) * 8;
    const uint32_t aXor = (uint32_t)(rA & 7);
    const uint32_t aRow = su + P1_A + (uint32_t)rA * 2048u;
    const uint32_t kcA = (uint32_t)(lane >> 4);
    const uint32_t bXor = (uint32_t)(lane & 7);
    const uint32_t kcB = (uint32_t)(lane >> 3);
    const uint32_t bR0 = su + P1_B + (uint32_t)(0  + (lane & 7)) * 2048u;
    const uint32_t bR1 = su + P1_B + (uint32_t)(8  + (lane & 7)) * 2048u;
    const uint32_t bR2 = su + P1_B + (uint32_t)(16 + (lane & 7)) * 2048u;
    float* s0 = (float*)(smem + P1_S);
    float* s1 = s0 + 1600;
    float* myS = kh ? s1 : s0;
    const int brow = mt * 16 + (lane >> 2);
    const int cc = (lane & 3) * 2;

    for (int db = 0; db < 128; ++db) {
        // B copy: 24 rows x 2KB from g_gw (verbatim)
        {
            const uint4* src = (const uint4*)(g_gw + (size_t)db * 24 * 1024);
            uint4* dst = (uint4*)(smem + P1_B);
            #pragma unroll
            for (int i = 0; i < 12; ++i) dst[tid + i * 256] = __ldg(src + tid + i * 256);
        }
        __syncthreads();

        float acc0[4] = {0.f, 0.f, 0.f, 0.f};
        float acc1[4] = {0.f, 0.f, 0.f, 0.f};
        float acc2[4] = {0.f, 0.f, 0.f, 0.f};
        if (kh == 0) { SEGRUN(0, 0, 0, 16)  SEGRUN(0, 512, 0, 8) }
        else         { SEGRUN(0, 512, 8, 16)  SEGRUN(512, 0, 0, 16) }

        #pragma unroll
        for (int gt = 0; gt < 3; ++gt) {
            float* a4 = (gt == 0) ? acc0 : (gt == 1) ? acc1 : acc2;
            myS[brow * 25 + gt * 8 + cc]           = a4[0];
            myS[brow * 25 + gt * 8 + cc + 1]       = a4[1];
            myS[(brow + 8) * 25 + gt * 8 + cc]     = a4[2];
            myS[(brow + 8) * 25 + gt * 8 + cc + 1] = a4[3];
        }
        __syncthreads();

        // G write: 2 t-blocks x 32 b x 24 cols = 384 float4
        for (int id = tid; id < 384; id += 256) {
            int tl = id / 192, rem = id - tl * 192;
            int b = rem / 6, f4 = rem - b * 6;
            int srow = tl * 32 + b, c0 = f4 * 4;
            float4 v;
            v.x = s0[srow * 25 + c0 + 0] + s1[srow * 25 + c0 + 0];
            v.y = s0[srow * 25 + c0 + 1] + s1[srow * 25 + c0 + 1];
            v.z = s0[srow * 25 + c0 + 2] + s1[srow * 25 + c0 + 2];
            v.w = s0[srow * 25 + c0 + 3] + s1[srow * 25 + c0 + 3];
            size_t go = ((((size_t)(tg * 2 + tl) * 2 + (db >> 6)) * NB + (db & 63)) * BB + b) * 24 + c0;
            *(float4*)&g_G[go] = v;
        }
        __syncthreads();
    }
}

// ----------------------------------------------------------------------------
// Main persistent recurrence: h-GEMM only. Warps: m-half(2) x k-quarter(4),
// 12 dd each. G preacts prefetched pre-poll. Scratch in dead x-region.
// ----------------------------------------------------------------------------
__global__ void __launch_bounds__(256, 1) gru_mma(Args p)
{
    extern __shared__ char smem[];
    const uint32_t su = smem_u32(smem);
    const int tid = threadIdx.x, wid = tid >> 5, lane = tid & 31;
    const int dir = blockIdx.x / NB, blk = blockIdx.x % NB, j0 = blk * CPB;

    // base read FIRST (minimize race window vs other CTAs' arrivals)
    unsigned base = 0;
    if (tid == 0) base = ld_acq(&g_root[dir]);

    // Whh prep: split-bf16, transposed, swizzled into SMEM B (one-time)
    for (int idx = tid; idx < 24 * 512; idx += 256) {
        int n = idx >> 9, k = idx & 511;
        int gate = n >> 3, jl = n & 7;
        float v = p.Whh[dir][gate][(size_t)k * HH + j0 + jl];
        unsigned short hb = cvtbf(v);
        unsigned short lb = cvtbf(v - __uint_as_float((unsigned)hb << 16));
        char* rowp = smem + SM_B + n * 2048;
        int ib = (k & 7) * 2, x7 = n & 7;
        *(unsigned short*)(rowp + (((k >> 3) ^ x7) << 4) + ib) = hb;
        *(unsigned short*)(rowp + ((((512 + k) >> 3) ^ x7) << 4) + ib) = lb;
    }

    // warp slices
    const int m0 = (wid & 1) * 16;
    const int kh = wid >> 1;                       // 0..3
    const int rA = m0 + (lane & 7) + ((lane >> 3) & 1) * 8;
    const uint32_t aXor = (uint32_t)(rA & 7);
    const uint32_t aRow = su + SM_A + (uint32_t)rA * 4096u;
    const uint32_t kcA = (uint32_t)(lane >> 4);
    const uint32_t bXor = (uint32_t)(lane & 7);
    const uint32_t kcB = (uint32_t)(lane >> 3);
    const uint32_t bR0 = su + SM_B + (uint32_t)(0  + (lane & 7)) * 2048u;
    const uint32_t bR1 = su + SM_B + (uint32_t)(8  + (lane & 7)) * 2048u;
    const uint32_t bR2 = su + SM_B + (uint32_t)(16 + (lane & 7)) * 2048u;
    const int scrBase = kh * 800;
    const int brow = m0 + (lane >> 2);
    const int cc = (lane & 3) * 2;

    // per-thread epilogue state: owns (b = tid>>3, jl = tid&7)
    const int eb = tid >> 3;
    const int ejl = tid & 7;
    const float cbr  = __ldg(&p.br [dir][j0 + ejl]);
    const float cbi  = __ldg(&p.bi [dir][j0 + ejl]);
    const float cbni = __ldg(&p.bni[dir][j0 + ejl]);
    const float cbnh = __ldg(&p.bnh[dir][j0 + ejl]);
    float hprev = 0.0f;

    // h0 = 0 planes
    if (tid < BB) {
        uint4 z = make_uint4(0u, 0u, 0u, 0u);
        *(uint4*)&g_hh[dir][0][tid * HH + j0] = z;
        *(uint4*)&g_hl[dir][0][tid * HH + j0] = z;
    }
    __syncthreads();
    if (tid == 0) net_arrive(dir, blk >> 3);

    float* out = p.out;

    for (int st = 0; st < TT; ++st) {
        const int t = dir ? (TT - 1 - st) : st;
        const int par = st & 1;

        // 1. prefetch this thread's gate preacts (independent of h; hides poll)
        const size_t gofs = ((((size_t)t * 2 + dir) * NB + blk) * BB + eb) * 24 + ejl;
        const float gr = __ldg(g_G + gofs);
        const float gc = __ldg(g_G + gofs + 8);
        const float gn = __ldg(g_G + gofs + 16);

        // 2. wait for h(st)
        if (tid == 0) {
            unsigned tgt = (unsigned)(8 * (st + 1));
            while (ld_acq(&g_root[dir]) - base < tgt) { }
        }
        __syncthreads();                           // S1

        // 3. stage h planes -> A h regions (raw swizzled copies)
        {
            const unsigned short* hhp = g_hh[dir][par];
            const unsigned short* hlp = g_hl[dir][par];
            #pragma unroll 4
            for (int i = 0; i < 8; ++i) {
                int id = tid + i * 256;
                int row = id >> 6, c8 = id & 63, x7 = row & 7;
                char* rowp = smem + SM_A + row * 4096;
                uint4 v = __ldcv((const uint4*)(hhp + row * HH + c8 * 8));
                *(uint4*)(rowp + (((c8 + 128) ^ x7) << 4)) = v;
                uint4 v2 = __ldcv((const uint4*)(hlp + row * HH + c8 * 8));
                *(uint4*)(rowp + (((c8 + 192) ^ x7) << 4)) = v2;
            }
        }
        __syncthreads();                           // S2

        // 4. h-GEMM: 12 dd per warp (3-term split over k-quarters)
        float acc0[4] = {0.f, 0.f, 0.f, 0.f};
        float acc1[4] = {0.f, 0.f, 0.f, 0.f};
        float acc2[4] = {0.f, 0.f, 0.f, 0.f};
        if (kh == 0)      { SEGRUN(1024, 0, 0, 12) }
        else if (kh == 1) { SEGRUN(1024, 0, 12, 16)  SEGRUN(1024, 512, 0, 8) }
        else if (kh == 2) { SEGRUN(1024, 512, 8, 16)  SEGRUN(1536, 0, 0, 4) }
        else              { SEGRUN(1536, 0, 4, 16) }

        // 5. immediate partial store (scratch region is dead x bytes)
        #pragma unroll
        for (int gt = 0; gt < 3; ++gt) {
            float* a4 = (gt == 0) ? acc0 : (gt == 1) ? acc1 : acc2;
            *scx(smem, scrBase + brow * 25 + gt * 8 + cc)           = a4[0];
            *scx(smem, scrBase + brow * 25 + gt * 8 + cc + 1)       = a4[1];
            *scx(smem, scrBase + (brow + 8) * 25 + gt * 8 + cc)     = a4[2];
            *scx(smem, scrBase + (brow + 8) * 25 + gt * 8 + cc + 1) = a4[3];
        }
        __syncthreads();                           // S3

        // 6. distributed epilogue
        {
            const int bx = eb * 25 + ejl;
            float ahr = *scx(smem, K0 + bx)      + *scx(smem, K1 + bx)
                      + *scx(smem, K2 + bx)      + *scx(smem, K3 + bx);
            float ahc = *scx(smem, K0 + bx + 8)  + *scx(smem, K1 + bx + 8)
                      + *scx(smem, K2 + bx + 8)  + *scx(smem, K3 + bx + 8);
            float ahn = *scx(smem, K0 + bx + 16) + *scx(smem, K1 + bx + 16)
                      + *scx(smem, K2 + bx + 16) + *scx(smem, K3 + bx + 16);
            float r = fsig(gr + ahr + cbr);
            float c = fsig(gc + ahc + cbi);
            float n = ftanh(gn + cbni + r * (ahn + cbnh));
            float hn = n + c * (hprev - n);
            hprev = hn;
            unsigned short hb = cvtbf(hn);
            unsigned short lb = cvtbf(hn - __uint_as_float((unsigned)hb << 16));
            g_hh[dir][par ^ 1][eb * HH + j0 + ejl] = hb;
            g_hl[dir][par ^ 1][eb * HH + j0 + ejl] = lb;
            out[((size_t)t * BB + eb) * (2 * HH) + dir * HH + j0 + ejl] = hn;
        }
        __syncthreads();                           // S4: stores before arrive
        if (tid == 0) net_arrive(dir, blk >> 3);
    }
}

// ----------------------------------------------------------------------------
// Launch. Input order: x, Wri_f,Wci_f,Wni_f,Wrh_f,Wch_f,Wnh_f,br_f,bi_f,bni_f,
// bnh_f, Wri_b,Wci_b,Wni_b,Wrh_b,Wch_b,Wnh_b,br_b,bi_b,bni_b,bnh_b
// ----------------------------------------------------------------------------
extern "C" void kernel_launch(void* const* d_in, const int* in_sizes, int n_in,
                              void* d_out, int out_size)
{
    (void)in_sizes; (void)n_in; (void)out_size;
    Args a;
    a.x = (const float*)d_in[0];
    a.Wxi[0][0] = (const float*)d_in[1];
    a.Wxi[0][1] = (const float*)d_in[2];
    a.Wxi[0][2] = (const float*)d_in[3];
    a.Whh[0][0] = (const float*)d_in[4];
    a.Whh[0][1] = (const float*)d_in[5];
    a.Whh[0][2] = (const float*)d_in[6];
    a.br [0] = (const float*)d_in[7];
    a.bi [0] = (const float*)d_in[8];
    a.bni[0] = (const float*)d_in[9];
    a.bnh[0] = (const float*)d_in[10];
    a.Wxi[1][0] = (const float*)d_in[11];
    a.Wxi[1][1] = (const float*)d_in[12];
    a.Wxi[1][2] = (const float*)d_in[13];
    a.Whh[1][0] = (const float*)d_in[14];
    a.Whh[1][1] = (const float*)d_in[15];
    a.Whh[1][2] = (const float*)d_in[16];
    a.br [1] = (const float*)d_in[17];
    a.bi [1] = (const float*)d_in[18];
    a.bni[1] = (const float*)d_in[19];
    a.bnh[1] = (const float*)d_in[20];
    a.out = (float*)d_out;

    prep_w<<<128, 256>>>(a);
    prep_x<<<16384, 256>>>(a.x);
    cudaFuncSetAttribute(prep_g, cudaFuncAttributeMaxDynamicSharedMemorySize, P1_TOT);
    prep_g<<<1024, 256, P1_TOT>>>();
    cudaFuncSetAttribute(gru_mma, cudaFuncAttributeMaxDynamicSharedMemorySize, SM_TOT);
    gru_mma<<<2 * NB, 256, SM_TOT>>>(a);
}